// round 4
// baseline (speedup 1.0000x reference)
#include <cuda_runtime.h>
#include <cuda_bf16.h>
#include <cstdint>

#define BATCH 4
#define NPTS  4096
#define DIM   64
#define LOG2E 1.4426950408889634f
#define SC_F  24.0224478f          // sqrt(log2e)/0.05
#define TWOL  2.8853900817779268f  // 2*log2e

#define BM 128
#define BN 128
#define NJT (NPTS/BN)   // 32
#define NIT (NPTS/BM)   // 32

#define ROWB 272                    // 256B packed row + 16B pad
#define OFF_A 0
#define SZ_A  (128*ROWB)            // 34816
#define OFF_B (SZ_A)
#define SZ_BB (128*ROWB)
#define OFF_P (OFF_B + 2*SZ_BB)     // 104448
#define SZ_P  2048
#define OFF_M (OFF_P + 4*SZ_P)      // 112640
#define OFF_R (OFF_M + 128*24)      // 115712
#define SMEM_TOTAL (OFF_R + 64)     // 115776

// scratch (no allocation allowed)
__device__ __align__(16) uint32_t g_pk1[BATCH*NPTS*64]; // [hi64|lo64] bf16, f1*2log2e
__device__ __align__(16) uint32_t g_pk2[BATCH*NPTS*64]; // [hi64|lo64] bf16, f2 raw
__device__ __align__(16) float4   g_pi[BATCH*NPTS];     // coords*SC
__device__ __align__(16) float4   g_pj[BATCH*NPTS];     // coords*SC, w = log2e*||f2||^2
__device__ float g_partial[BATCH*NIT];

__device__ __forceinline__ float ex2(float x){
    float y; asm("ex2.approx.ftz.f32 %0, %1;" : "=f"(y) : "f"(x)); return y;
}
__device__ __forceinline__ void cpa16(uint32_t dst, const void* src){
    asm volatile("cp.async.cg.shared.global [%0], [%1], 16;\n" :: "r"(dst), "l"(src));
}
__device__ __forceinline__ void ldmx4(uint32_t& r0,uint32_t& r1,uint32_t& r2,uint32_t& r3, uint32_t a){
    asm volatile("ldmatrix.sync.aligned.m8n8.x4.shared.b16 {%0,%1,%2,%3}, [%4];\n"
                 : "=r"(r0),"=r"(r1),"=r"(r2),"=r"(r3) : "r"(a));
}
__device__ __forceinline__ void mma16816(float* c, const uint32_t* a, uint32_t b0, uint32_t b1){
    asm volatile("mma.sync.aligned.m16n8k16.row.col.f32.bf16.bf16.f32 "
                 "{%0,%1,%2,%3}, {%4,%5,%6,%7}, {%8,%9}, {%0,%1,%2,%3};\n"
                 : "+f"(c[0]),"+f"(c[1]),"+f"(c[2]),"+f"(c[3])
                 : "r"(a[0]),"r"(a[1]),"r"(a[2]),"r"(a[3]), "r"(b0),"r"(b1));
}

// ---------------------------------------------------------------------------
__global__ void prep_kernel(const float* __restrict__ pts,
                            const float* __restrict__ f1,
                            const float* __restrict__ f2)
{
    int gw   = (blockIdx.x*blockDim.x + threadIdx.x) >> 5;
    int lane = threadIdx.x & 31;
    if (gw >= BATCH*NPTS) return;
    const float* r1 = f1 + (size_t)gw*DIM;
    const float* r2 = f2 + (size_t)gw*DIM;
    float a0 = r1[lane], a1 = r1[lane+32];
    float b0 = r2[lane], b1 = r2[lane+32];
    float n2 = b0*b0 + b1*b1;
    #pragma unroll
    for (int o=16;o>=1;o>>=1) n2 += __shfl_xor_sync(~0u,n2,o);

    float s0 = a0*TWOL, s1 = a1*TWOL;
    __nv_bfloat16 h0=__float2bfloat16(s0), h1=__float2bfloat16(s1);
    __nv_bfloat16 l0=__float2bfloat16(s0-__bfloat162float(h0));
    __nv_bfloat16 l1=__float2bfloat16(s1-__bfloat162float(h1));
    __nv_bfloat16* o1 = (__nv_bfloat16*)(g_pk1 + (size_t)gw*64);
    o1[lane]=h0; o1[32+lane]=h1; o1[64+lane]=l0; o1[96+lane]=l1;

    __nv_bfloat16 H0=__float2bfloat16(b0), H1=__float2bfloat16(b1);
    __nv_bfloat16 L0=__float2bfloat16(b0-__bfloat162float(H0));
    __nv_bfloat16 L1=__float2bfloat16(b1-__bfloat162float(H1));
    __nv_bfloat16* o2 = (__nv_bfloat16*)(g_pk2 + (size_t)gw*64);
    o2[lane]=H0; o2[32+lane]=H1; o2[64+lane]=L0; o2[96+lane]=L1;

    if (lane==0){
        float px = pts[(size_t)gw*3+0]*SC_F;
        float py = pts[(size_t)gw*3+1]*SC_F;
        float pz = pts[(size_t)gw*3+2]*SC_F;
        g_pi[gw] = make_float4(px,py,pz,0.0f);
        g_pj[gw] = make_float4(px,py,pz,n2*LOG2E);
    }
}

// ---------------------------------------------------------------------------
__device__ __forceinline__ void do_mma(float (&acc)[2][8][4], uint32_t aAddr,
                                       uint32_t pB, int bn_row, uint32_t bk16)
{
    #pragma unroll
    for(int mb=0;mb<2;mb++)
        #pragma unroll
        for(int nb=0;nb<8;nb++)
            #pragma unroll
            for(int q=0;q<4;q++) acc[mb][nb][q]=0.f;
    #pragma unroll
    for(int kb=0;kb<12;kb++){
        const int offA = ((kb&3)<<5) + ((kb>=8)?128:0);
        const int offB = (kb<4)? (kb<<5) : ((kb<8)? (128+((kb-4)<<5)) : ((kb-8)<<5));
        uint32_t a[2][4];
        ldmx4(a[0][0],a[0][1],a[0][2],a[0][3], aAddr + offA);
        ldmx4(a[1][0],a[1][1],a[1][2],a[1][3], aAddr + 16*ROWB + offA);
        uint32_t bb[4][4];
        #pragma unroll
        for(int n2=0;n2<4;n2++)
            ldmx4(bb[n2][0],bb[n2][1],bb[n2][2],bb[n2][3],
                  pB + (n2*16 + bn_row)*ROWB + bk16 + offB);
        #pragma unroll
        for(int mb=0;mb<2;mb++)
            #pragma unroll
            for(int n2=0;n2<4;n2++){
                mma16816(acc[mb][n2*2  ], a[mb], bb[n2][0], bb[n2][1]);
                mma16816(acc[mb][n2*2+1], a[mb], bb[n2][2], bb[n2][3]);
            }
    }
}

__device__ __forceinline__ void do_epilogue(
    float (&acc)[2][8][4], const char* smem, int pslot, int wx, int tig,
    const float (&x2x)[4], const float (&x2y)[4], const float (&x2z)[4], const float (&nni)[4],
    float (&m2s)[4], float (&Z1s)[4], float (&Z2s)[4],
    float (&As)[4], float (&Bs)[4], float (&Cs)[4])
{
    const float*  pW = (const float*)(smem + OFF_P + pslot*SZ_P);
    const float4* pP = (const float4*)pW;
    // per-thread min of cn2 over my 16 cols (for a safe per-tile max bound)
    float mn = 3.0e38f;
    #pragma unroll
    for(int nb=0;nb<8;nb++){
        int c0 = wx*64 + nb*8 + tig*2;
        mn = fminf(mn, fminf(pW[c0*4+3], pW[(c0+1)*4+3]));
    }
    #pragma unroll
    for(int si=0;si<4;si++){
        int mb=si>>1, rp=si&1;
        float mx = -3.0e38f;
        #pragma unroll
        for(int nb=0;nb<8;nb++)
            mx = fmaxf(mx, fmaxf(acc[mb][nb][rp*2], acc[mb][nb][rp*2+1]));
        float m2n = fmaxf(m2s[si], mx - mn);
        float c2 = ex2(m2s[si] - m2n);
        Z2s[si]*=c2; Cs[si]*=c2; Bs[si]*=c2*c2; m2s[si]=m2n;
    }
    #pragma unroll
    for(int nb=0;nb<8;nb++){
        #pragma unroll
        for(int qq=0;qq<2;qq++){
            int c = wx*64 + nb*8 + tig*2 + qq;
            float4 v = pP[c];
            float njc = fmaf(v.x,v.x, fmaf(v.y,v.y, v.z*v.z));   // hoisted per col
            #pragma unroll
            for(int si=0;si<4;si++){
                int mb=si>>1, rp=si&1;
                float t = fmaf(x2x[si], v.x, fmaf(x2y[si], v.y,
                          fmaf(x2z[si], v.z, nni[si] - njc)));
                float e1 = ex2(t);
                float e2 = ex2((acc[mb][nb][rp*2+qq] - v.w) - m2s[si]);
                Z1s[si]+=e1; As[si]=fmaf(e1,e1,As[si]);
                Z2s[si]+=e2; Bs[si]=fmaf(e2,e2,Bs[si]);
                Cs[si]=fmaf(e1,e2,Cs[si]);
            }
        }
    }
}

// ---------------------------------------------------------------------------
// 256 threads = 8 warps (wy 0..3 x wx 0..1); warp tile 32 rows x 64 cols.
// Cross-tile pipeline: MMA(tile t+1) interleaved with epilogue(tile t).
// ---------------------------------------------------------------------------
__global__ __launch_bounds__(256,1)
void loss_kernel(const float* __restrict__ wts)
{
    extern __shared__ __align__(16) char smem[];
    const uint32_t sb = (uint32_t)__cvta_generic_to_shared(smem);
    const int b  = blockIdx.y;
    const int i0 = blockIdx.x*BM;
    const int tid = threadIdx.x;
    const int w = tid>>5, lane = tid&31;
    const int wy = w>>1, wx = w&1;
    const int g = lane>>2, tig = lane&3;

    // prologue: A + B0 + P0 (group0), B1 + P1 (group1)
    {
        const char* gA = (const char*)(g_pk1 + (size_t)(b*NPTS+i0)*64);
        const char* gB0 = (const char*)(g_pk2 + (size_t)(b*NPTS)*64);
        #pragma unroll
        for(int q=0;q<8;q++){
            int idx=q*256+tid, r=idx>>4, c=idx&15;
            cpa16(sb + OFF_A + r*ROWB + c*16, gA + r*256 + c*16);
            cpa16(sb + OFF_B + r*ROWB + c*16, gB0 + r*256 + c*16);
        }
        if (tid<128) cpa16(sb + OFF_P + tid*16, (const char*)(g_pj + b*NPTS + tid));
        asm volatile("cp.async.commit_group;\n");
        const char* gB1 = (const char*)(g_pk2 + (size_t)(b*NPTS + BN)*64);
        #pragma unroll
        for(int q=0;q<8;q++){
            int idx=q*256+tid, r=idx>>4, c=idx&15;
            cpa16(sb + OFF_B + SZ_BB + r*ROWB + c*16, gB1 + r*256 + c*16);
        }
        if (tid<128) cpa16(sb + OFF_P + SZ_P + tid*16, (const char*)(g_pj + b*NPTS + BN + tid));
        asm volatile("cp.async.commit_group;\n");
    }

    const uint32_t aAddr = sb + OFF_A + (wy*32 + (lane&15))*ROWB + (lane>>4)*16;
    const int bn_row = (lane&7) + (((lane>>4)&1)<<3);
    const uint32_t bk16 = ((lane>>3)&1)*16;
    const uint32_t pBbase = sb + OFF_B + wx*64*ROWB;

    float x2x[4],x2y[4],x2z[4],nni[4]; int rl_[4];
    #pragma unroll
    for(int si=0;si<4;si++){
        int mb=si>>1, rp=si&1;
        int rl = wy*32 + mb*16 + rp*8 + g;
        rl_[si]=rl;
        float4 v = g_pi[b*NPTS + i0 + rl];
        x2x[si]=v.x+v.x; x2y[si]=v.y+v.y; x2z[si]=v.z+v.z;
        nni[si]=-fmaf(v.x,v.x, fmaf(v.y,v.y, v.z*v.z));
    }
    float m2s[4],Z1s[4],Z2s[4],As[4],Bs[4],Cs[4];
    #pragma unroll
    for(int si=0;si<4;si++){ m2s[si]=-3.0e38f; Z1s[si]=0.f;Z2s[si]=0.f;As[si]=0.f;Bs[si]=0.f;Cs[si]=0.f; }

    float accA[2][8][4], accB[2][8][4];

    // tile 0 MMA (group1 may still be in flight)
    asm volatile("cp.async.wait_group 1;\n" ::: "memory");
    __syncthreads();
    do_mma(accA, aAddr, pBbase, bn_row, bk16);

    #pragma unroll 2
    for(int jt=0; jt<NJT; jt++){
        if (jt+1 < NJT){
            asm volatile("cp.async.wait_group 0;\n" ::: "memory");
        }
        __syncthreads();
        if (jt+2 < NJT){
            const char* gB = (const char*)(g_pk2 + (size_t)(b*NPTS + (jt+2)*BN)*64);
            const uint32_t dstB = sb + OFF_B + ((jt+2)&1)*SZ_BB;
            #pragma unroll
            for(int q=0;q<8;q++){
                int idx=q*256+tid, r=idx>>4, c=idx&15;
                cpa16(dstB + r*ROWB + c*16, gB + r*256 + c*16);
            }
            if (tid<128) cpa16(sb + OFF_P + ((jt+2)&3)*SZ_P + tid*16,
                               (const char*)(g_pj + b*NPTS + (jt+2)*BN + tid));
            asm volatile("cp.async.commit_group;\n");
        }
        if ((jt&1)==0){
            if (jt+1 < NJT) do_mma(accB, aAddr, pBbase + SZ_BB*((jt+1)&1), bn_row, bk16);
            do_epilogue(accA, smem, jt&3, wx, tig, x2x,x2y,x2z,nni,
                        m2s,Z1s,Z2s,As,Bs,Cs);
        } else {
            if (jt+1 < NJT) do_mma(accA, aAddr, pBbase + SZ_BB*((jt+1)&1), bn_row, bk16);
            do_epilogue(accB, smem, jt&3, wx, tig, x2x,x2y,x2z,nni,
                        m2s,Z1s,Z2s,As,Bs,Cs);
        }
    }

    // ---- merge 4 tig-lanes per row ----
    #pragma unroll
    for(int si=0;si<4;si++){
        #pragma unroll
        for(int off=1; off<=2; off<<=1){
            float om = __shfl_xor_sync(~0u, m2s[si], off);
            float oZ2= __shfl_xor_sync(~0u, Z2s[si], off);
            float oB = __shfl_xor_sync(~0u, Bs[si], off);
            float oC = __shfl_xor_sync(~0u, Cs[si], off);
            float oZ1= __shfl_xor_sync(~0u, Z1s[si], off);
            float oA = __shfl_xor_sync(~0u, As[si], off);
            float nm = fmaxf(m2s[si], om);
            float c = ex2(m2s[si]-nm), d = ex2(om-nm);
            Z2s[si]=Z2s[si]*c + oZ2*d;
            Bs[si]=Bs[si]*c*c + oB*d*d;
            Cs[si]=Cs[si]*c + oC*d;
            Z1s[si]+=oZ1; As[si]+=oA;
            m2s[si]=nm;
        }
    }
    // ---- merge wx pair via smem ----
    float* sM = (float*)(smem + OFF_M);
    float* sR = (float*)(smem + OFF_R);
    if (wx==1 && tig==0){
        #pragma unroll
        for(int si=0;si<4;si++){
            float* p = sM + rl_[si]*6;
            p[0]=m2s[si]; p[1]=Z2s[si]; p[2]=Bs[si]; p[3]=Cs[si]; p[4]=Z1s[si]; p[5]=As[si];
        }
    }
    __syncthreads();
    float wacc = 0.0f;
    if (wx==0 && tig==0){
        #pragma unroll
        for(int si=0;si<4;si++){
            const float* p = sM + rl_[si]*6;
            float om=p[0], oZ2=p[1], oB=p[2], oC=p[3], oZ1=p[4], oA=p[5];
            float nm = fmaxf(m2s[si], om);
            float c = ex2(m2s[si]-nm), d = ex2(om-nm);
            float Z2 = Z2s[si]*c + oZ2*d;
            float Bv = Bs[si]*c*c + oB*d*d;
            float Cv = Cs[si]*c + oC*d;
            float Z1 = Z1s[si] + oZ1;
            float Av = As[si] + oA;
            float i1 = 1.0f/Z1, i2 = 1.0f/Z2;
            float loss = Av*i1*i1 - 2.0f*Cv*i1*i2 + Bv*i2*i2;
            wacc += wts[b*NPTS + i0 + rl_[si]] * loss;
        }
    }
    #pragma unroll
    for(int off=16; off>=1; off>>=1) wacc += __shfl_xor_sync(~0u, wacc, off);
    if (wx==0 && lane==0) sR[wy] = wacc;
    __syncthreads();
    if (tid==0)
        g_partial[b*NIT + blockIdx.x] = (sR[0]+sR[1]) + (sR[2]+sR[3]);
}

// ---------------------------------------------------------------------------
__global__ void reduce_kernel(float* __restrict__ out)
{
    int b    = threadIdx.x >> 5;
    int lane = threadIdx.x & 31;
    float s = g_partial[b*NIT + lane];
    #pragma unroll
    for(int off=16; off>=1; off>>=1) s += __shfl_xor_sync(~0u, s, off);
    if (lane==0) out[b] = s;
}

// ---------------------------------------------------------------------------
extern "C" void kernel_launch(void* const* d_in, const int* in_sizes, int n_in,
                              void* d_out, int out_size)
{
    const float* pts = (const float*)d_in[0];
    const float* wts = (const float*)d_in[1];
    const float* f1  = (const float*)d_in[2];
    const float* f2  = (const float*)d_in[3];
    float* out = (float*)d_out;

    cudaFuncSetAttribute(loss_kernel, cudaFuncAttributeMaxDynamicSharedMemorySize, SMEM_TOTAL);
    prep_kernel<<<(BATCH*NPTS)/8, 256>>>(pts, f1, f2);
    dim3 grid(NIT, BATCH);
    loss_kernel<<<grid, 256, SMEM_TOTAL>>>(wts);
    reduce_kernel<<<1, 128>>>(out);
}

// round 7
// speedup vs baseline: 1.0335x; 1.0335x over previous
#include <cuda_runtime.h>
#include <cuda_bf16.h>
#include <cstdint>

#define BATCH 4
#define NPTS  4096
#define DIM   64
#define LOG2E 1.4426950408889634f
#define SC_F  24.0224478f          // sqrt(log2e)/0.05
#define TWOL  2.8853900817779268f  // 2*log2e

#define BM 128
#define BN 64
#define NJT (NPTS/BN)   // 64
#define NIT (NPTS/BM)   // 32

#define ROWB 272                    // 256B packed row + 16B pad
#define OFF_A 0
#define SZ_A  (128*ROWB)            // 34816
#define OFF_B (SZ_A)
#define SZ_BB (64*ROWB)             // 17408
#define OFF_P (OFF_B + 2*SZ_BB)     // 69632
#define SZ_P  1024
#define OFF_M (OFF_P + 4*SZ_P)      // 73728
#define OFF_R (OFF_M + 128*24)      // 76800
#define SMEM_TOTAL (OFF_R + 64)     // 76864

// scratch (no allocation allowed)
__device__ __align__(16) uint32_t g_pk1[BATCH*NPTS*64]; // [hi64|lo64] bf16, f1*2log2e
__device__ __align__(16) uint32_t g_pk2[BATCH*NPTS*64]; // [hi64|lo64] bf16, f2 raw
__device__ __align__(16) float4   g_pi[BATCH*NPTS];     // coords*SC
__device__ __align__(16) float4   g_pj[BATCH*NPTS];     // coords*SC, w = log2e*||f2||^2
__device__ float g_partial[BATCH*NIT];

__device__ __forceinline__ float ex2(float x){
    float y; asm("ex2.approx.ftz.f32 %0, %1;" : "=f"(y) : "f"(x)); return y;
}
__device__ __forceinline__ void cpa16(uint32_t dst, const void* src){
    asm volatile("cp.async.cg.shared.global [%0], [%1], 16;\n" :: "r"(dst), "l"(src));
}
__device__ __forceinline__ void ldmx4(uint32_t& r0,uint32_t& r1,uint32_t& r2,uint32_t& r3, uint32_t a){
    asm volatile("ldmatrix.sync.aligned.m8n8.x4.shared.b16 {%0,%1,%2,%3}, [%4];\n"
                 : "=r"(r0),"=r"(r1),"=r"(r2),"=r"(r3) : "r"(a));
}
__device__ __forceinline__ void mma16816(float* c, const uint32_t* a, uint32_t b0, uint32_t b1){
    asm volatile("mma.sync.aligned.m16n8k16.row.col.f32.bf16.bf16.f32 "
                 "{%0,%1,%2,%3}, {%4,%5,%6,%7}, {%8,%9}, {%0,%1,%2,%3};\n"
                 : "+f"(c[0]),"+f"(c[1]),"+f"(c[2]),"+f"(c[3])
                 : "r"(a[0]),"r"(a[1]),"r"(a[2]),"r"(a[3]), "r"(b0),"r"(b1));
}

// ---------------------------------------------------------------------------
__global__ void prep_kernel(const float* __restrict__ pts,
                            const float* __restrict__ f1,
                            const float* __restrict__ f2)
{
    int gw   = (blockIdx.x*blockDim.x + threadIdx.x) >> 5;
    int lane = threadIdx.x & 31;
    if (gw >= BATCH*NPTS) return;
    const float* r1 = f1 + (size_t)gw*DIM;
    const float* r2 = f2 + (size_t)gw*DIM;
    float a0 = r1[lane], a1 = r1[lane+32];
    float b0 = r2[lane], b1 = r2[lane+32];
    float n2 = b0*b0 + b1*b1;
    #pragma unroll
    for (int o=16;o>=1;o>>=1) n2 += __shfl_xor_sync(~0u,n2,o);

    float s0 = a0*TWOL, s1 = a1*TWOL;
    __nv_bfloat16 h0=__float2bfloat16(s0), h1=__float2bfloat16(s1);
    __nv_bfloat16 l0=__float2bfloat16(s0-__bfloat162float(h0));
    __nv_bfloat16 l1=__float2bfloat16(s1-__bfloat162float(h1));
    __nv_bfloat16* o1 = (__nv_bfloat16*)(g_pk1 + (size_t)gw*64);
    o1[lane]=h0; o1[32+lane]=h1; o1[64+lane]=l0; o1[96+lane]=l1;

    __nv_bfloat16 H0=__float2bfloat16(b0), H1=__float2bfloat16(b1);
    __nv_bfloat16 L0=__float2bfloat16(b0-__bfloat162float(H0));
    __nv_bfloat16 L1=__float2bfloat16(b1-__bfloat162float(H1));
    __nv_bfloat16* o2 = (__nv_bfloat16*)(g_pk2 + (size_t)gw*64);
    o2[lane]=H0; o2[32+lane]=H1; o2[64+lane]=L0; o2[96+lane]=L1;

    if (lane==0){
        float px = pts[(size_t)gw*3+0]*SC_F;
        float py = pts[(size_t)gw*3+1]*SC_F;
        float pz = pts[(size_t)gw*3+2]*SC_F;
        g_pi[gw] = make_float4(px,py,pz,0.0f);
        g_pj[gw] = make_float4(px,py,pz,n2*LOG2E);
    }
}

// ---------------------------------------------------------------------------
// MMA for 32x32 warp tile with fragment reuse: 4 k16-chunks x {HH,HL,LH}.
// 8 ldmatrix.x4 + 24 mma per chunk-group.
// ---------------------------------------------------------------------------
__device__ __forceinline__ void do_mma(float (&acc)[2][4][4], uint32_t aAddr,
                                       uint32_t pB, int bn_row, uint32_t bk16)
{
    #pragma unroll
    for(int mb=0;mb<2;mb++)
        #pragma unroll
        for(int nb=0;nb<4;nb++)
            #pragma unroll
            for(int q=0;q<4;q++) acc[mb][nb][q]=0.f;
    #pragma unroll
    for(int c=0;c<4;c++){
        const int oh = c<<5;            // hi chunk offset
        const int ol = 128 + (c<<5);    // lo chunk offset
        uint32_t ah[2][4], al[2][4], bh[2][4], bl[2][4];
        ldmx4(ah[0][0],ah[0][1],ah[0][2],ah[0][3], aAddr + oh);
        ldmx4(ah[1][0],ah[1][1],ah[1][2],ah[1][3], aAddr + 16*ROWB + oh);
        ldmx4(al[0][0],al[0][1],al[0][2],al[0][3], aAddr + ol);
        ldmx4(al[1][0],al[1][1],al[1][2],al[1][3], aAddr + 16*ROWB + ol);
        #pragma unroll
        for(int n2=0;n2<2;n2++){
            uint32_t ba = pB + (n2*16 + bn_row)*ROWB + bk16;
            ldmx4(bh[n2][0],bh[n2][1],bh[n2][2],bh[n2][3], ba + oh);
            ldmx4(bl[n2][0],bl[n2][1],bl[n2][2],bl[n2][3], ba + ol);
        }
        #pragma unroll
        for(int mb=0;mb<2;mb++)
            #pragma unroll
            for(int n2=0;n2<2;n2++){
                mma16816(acc[mb][n2*2  ], ah[mb], bh[n2][0], bh[n2][1]);
                mma16816(acc[mb][n2*2+1], ah[mb], bh[n2][2], bh[n2][3]);
                mma16816(acc[mb][n2*2  ], ah[mb], bl[n2][0], bl[n2][1]);
                mma16816(acc[mb][n2*2+1], ah[mb], bl[n2][2], bl[n2][3]);
                mma16816(acc[mb][n2*2  ], al[mb], bh[n2][0], bh[n2][1]);
                mma16816(acc[mb][n2*2+1], al[mb], bh[n2][2], bh[n2][3]);
            }
    }
}

__device__ __forceinline__ void do_epilogue(
    float (&acc)[2][4][4], const char* smem, int pslot, int wx, int tig,
    const float (&x2x)[4], const float (&x2y)[4], const float (&x2z)[4], const float (&nni)[4],
    float (&m2s)[4], float (&Z1s)[4], float (&Z2s)[4],
    float (&As)[4], float (&Bs)[4], float (&Cs)[4])
{
    const float*  pW = (const float*)(smem + OFF_P + pslot*SZ_P);
    const float4* pP = (const float4*)pW;
    // per-thread min of cn2 over my 8 cols (safe per-tile max bound)
    float mn = 3.0e38f;
    #pragma unroll
    for(int nb=0;nb<4;nb++){
        int c0 = wx*32 + nb*8 + tig*2;
        mn = fminf(mn, fminf(pW[c0*4+3], pW[(c0+1)*4+3]));
    }
    #pragma unroll
    for(int si=0;si<4;si++){
        int mb=si>>1, rp=si&1;
        float mx = -3.0e38f;
        #pragma unroll
        for(int nb=0;nb<4;nb++)
            mx = fmaxf(mx, fmaxf(acc[mb][nb][rp*2], acc[mb][nb][rp*2+1]));
        float m2n = fmaxf(m2s[si], mx - mn);
        float c2 = ex2(m2s[si] - m2n);
        Z2s[si]*=c2; Cs[si]*=c2; Bs[si]*=c2*c2; m2s[si]=m2n;
    }
    #pragma unroll
    for(int nb=0;nb<4;nb++){
        #pragma unroll
        for(int qq=0;qq<2;qq++){
            int c = wx*32 + nb*8 + tig*2 + qq;
            float4 v = pP[c];
            float njc = fmaf(v.x,v.x, fmaf(v.y,v.y, v.z*v.z));
            #pragma unroll
            for(int si=0;si<4;si++){
                int mb=si>>1, rp=si&1;
                float t = fmaf(x2x[si], v.x, fmaf(x2y[si], v.y,
                          fmaf(x2z[si], v.z, nni[si] - njc)));
                float e1 = ex2(t);
                float e2 = ex2((acc[mb][nb][rp*2+qq] - v.w) - m2s[si]);
                Z1s[si]+=e1; As[si]=fmaf(e1,e1,As[si]);
                Z2s[si]+=e2; Bs[si]=fmaf(e2,e2,Bs[si]);
                Cs[si]=fmaf(e1,e2,Cs[si]);
            }
        }
    }
}

// ---------------------------------------------------------------------------
// 256 threads = 8 warps (wy 0..3 x wx 0..1); warp tile 32 rows x 32 cols.
// Cross-tile pipeline: MMA(t+1) and epilogue(t) in one region, disjoint regs.
// ---------------------------------------------------------------------------
__global__ __launch_bounds__(256,1)
void loss_kernel(const float* __restrict__ wts)
{
    extern __shared__ __align__(16) char smem[];
    const uint32_t sb = (uint32_t)__cvta_generic_to_shared(smem);
    const int b  = blockIdx.y;
    const int i0 = blockIdx.x*BM;
    const int tid = threadIdx.x;
    const int w = tid>>5, lane = tid&31;
    const int wy = w>>1, wx = w&1;
    const int g = lane>>2, tig = lane&3;

    // prologue: A + B0 + P0 (group0), B1 + P1 (group1)
    {
        const char* gA  = (const char*)(g_pk1 + (size_t)(b*NPTS+i0)*64);
        const char* gB0 = (const char*)(g_pk2 + (size_t)(b*NPTS)*64);
        #pragma unroll
        for(int q=0;q<8;q++){
            int idx=q*256+tid, r=idx>>4, c=idx&15;
            cpa16(sb + OFF_A + r*ROWB + c*16, gA + r*256 + c*16);
        }
        #pragma unroll
        for(int q=0;q<4;q++){
            int idx=q*256+tid, r=idx>>4, c=idx&15;
            cpa16(sb + OFF_B + r*ROWB + c*16, gB0 + r*256 + c*16);
        }
        if (tid<64) cpa16(sb + OFF_P + tid*16, (const char*)(g_pj + b*NPTS + tid));
        asm volatile("cp.async.commit_group;\n");
        const char* gB1 = (const char*)(g_pk2 + (size_t)(b*NPTS + BN)*64);
        #pragma unroll
        for(int q=0;q<4;q++){
            int idx=q*256+tid, r=idx>>4, c=idx&15;
            cpa16(sb + OFF_B + SZ_BB + r*ROWB + c*16, gB1 + r*256 + c*16);
        }
        if (tid<64) cpa16(sb + OFF_P + SZ_P + tid*16, (const char*)(g_pj + b*NPTS + BN + tid));
        asm volatile("cp.async.commit_group;\n");
    }

    const uint32_t aAddr = sb + OFF_A + (wy*32 + (lane&15))*ROWB + (lane>>4)*16;
    const int bn_row = (lane&7) + (((lane>>4)&1)<<3);
    const uint32_t bk16 = ((lane>>3)&1)*16;
    const uint32_t pBbase = sb + OFF_B + wx*32*ROWB;

    float x2x[4],x2y[4],x2z[4],nni[4]; int rl_[4];
    #pragma unroll
    for(int si=0;si<4;si++){
        int mb=si>>1, rp=si&1;
        int rl = wy*32 + mb*16 + rp*8 + g;
        rl_[si]=rl;
        float4 v = g_pi[b*NPTS + i0 + rl];
        x2x[si]=v.x+v.x; x2y[si]=v.y+v.y; x2z[si]=v.z+v.z;
        nni[si]=-fmaf(v.x,v.x, fmaf(v.y,v.y, v.z*v.z));
    }
    float m2s[4],Z1s[4],Z2s[4],As[4],Bs[4],Cs[4];
    #pragma unroll
    for(int si=0;si<4;si++){ m2s[si]=-3.0e38f; Z1s[si]=0.f;Z2s[si]=0.f;As[si]=0.f;Bs[si]=0.f;Cs[si]=0.f; }

    float accA[2][4][4], accB[2][4][4];

    // tile 0 MMA (group1 may still be in flight)
    asm volatile("cp.async.wait_group 1;\n" ::: "memory");
    __syncthreads();
    do_mma(accA, aAddr, pBbase, bn_row, bk16);

    for(int jt=0; jt<NJT; jt++){
        if (jt+1 < NJT){
            asm volatile("cp.async.wait_group 0;\n" ::: "memory");
        }
        __syncthreads();
        if (jt+2 < NJT){
            const char* gB = (const char*)(g_pk2 + (size_t)(b*NPTS + (jt+2)*BN)*64);
            const uint32_t dstB = sb + OFF_B + ((jt+2)&1)*SZ_BB;
            #pragma unroll
            for(int q=0;q<4;q++){
                int idx=q*256+tid, r=idx>>4, c=idx&15;
                cpa16(dstB + r*ROWB + c*16, gB + r*256 + c*16);
            }
            if (tid<64) cpa16(sb + OFF_P + ((jt+2)&3)*SZ_P + tid*16,
                              (const char*)(g_pj + b*NPTS + (jt+2)*BN + tid));
            asm volatile("cp.async.commit_group;\n");
        }
        if ((jt&1)==0){
            if (jt+1 < NJT) do_mma(accB, aAddr, pBbase + SZ_BB*((jt+1)&1), bn_row, bk16);
            do_epilogue(accA, smem, jt&3, wx, tig, x2x,x2y,x2z,nni,
                        m2s,Z1s,Z2s,As,Bs,Cs);
        } else {
            if (jt+1 < NJT) do_mma(accA, aAddr, pBbase + SZ_BB*((jt+1)&1), bn_row, bk16);
            do_epilogue(accB, smem, jt&3, wx, tig, x2x,x2y,x2z,nni,
                        m2s,Z1s,Z2s,As,Bs,Cs);
        }
    }

    // ---- merge 4 tig-lanes per row ----
    #pragma unroll
    for(int si=0;si<4;si++){
        #pragma unroll
        for(int off=1; off<=2; off<<=1){
            float om = __shfl_xor_sync(~0u, m2s[si], off);
            float oZ2= __shfl_xor_sync(~0u, Z2s[si], off);
            float oB = __shfl_xor_sync(~0u, Bs[si], off);
            float oC = __shfl_xor_sync(~0u, Cs[si], off);
            float oZ1= __shfl_xor_sync(~0u, Z1s[si], off);
            float oA = __shfl_xor_sync(~0u, As[si], off);
            float nm = fmaxf(m2s[si], om);
            float c = ex2(m2s[si]-nm), d = ex2(om-nm);
            Z2s[si]=Z2s[si]*c + oZ2*d;
            Bs[si]=Bs[si]*c*c + oB*d*d;
            Cs[si]=Cs[si]*c + oC*d;
            Z1s[si]+=oZ1; As[si]+=oA;
            m2s[si]=nm;
        }
    }
    // ---- merge wx pair via smem ----
    float* sM = (float*)(smem + OFF_M);
    float* sR = (float*)(smem + OFF_R);
    if (wx==1 && tig==0){
        #pragma unroll
        for(int si=0;si<4;si++){
            float* p = sM + rl_[si]*6;
            p[0]=m2s[si]; p[1]=Z2s[si]; p[2]=Bs[si]; p[3]=Cs[si]; p[4]=Z1s[si]; p[5]=As[si];
        }
    }
    __syncthreads();
    float wacc = 0.0f;
    if (wx==0 && tig==0){
        #pragma unroll
        for(int si=0;si<4;si++){
            const float* p = sM + rl_[si]*6;
            float om=p[0], oZ2=p[1], oB=p[2], oC=p[3], oZ1=p[4], oA=p[5];
            float nm = fmaxf(m2s[si], om);
            float c = ex2(m2s[si]-nm), d = ex2(om-nm);
            float Z2 = Z2s[si]*c + oZ2*d;
            float Bv = Bs[si]*c*c + oB*d*d;
            float Cv = Cs[si]*c + oC*d;
            float Z1 = Z1s[si] + oZ1;
            float Av = As[si] + oA;
            float i1 = 1.0f/Z1, i2 = 1.0f/Z2;
            float loss = Av*i1*i1 - 2.0f*Cv*i1*i2 + Bv*i2*i2;
            wacc += wts[b*NPTS + i0 + rl_[si]] * loss;
        }
    }
    #pragma unroll
    for(int off=16; off>=1; off>>=1) wacc += __shfl_xor_sync(~0u, wacc, off);
    if (wx==0 && lane==0) sR[wy] = wacc;
    __syncthreads();
    if (tid==0)
        g_partial[b*NIT + blockIdx.x] = (sR[0]+sR[1]) + (sR[2]+sR[3]);
}

// ---------------------------------------------------------------------------
__global__ void reduce_kernel(float* __restrict__ out)
{
    int b    = threadIdx.x >> 5;
    int lane = threadIdx.x & 31;
    float s = g_partial[b*NIT + lane];
    #pragma unroll
    for(int off=16; off>=1; off>>=1) s += __shfl_xor_sync(~0u, s, off);
    if (lane==0) out[b] = s;
}

// ---------------------------------------------------------------------------
extern "C" void kernel_launch(void* const* d_in, const int* in_sizes, int n_in,
                              void* d_out, int out_size)
{
    const float* pts = (const float*)d_in[0];
    const float* wts = (const float*)d_in[1];
    const float* f1  = (const float*)d_in[2];
    const float* f2  = (const float*)d_in[3];
    float* out = (float*)d_out;

    cudaFuncSetAttribute(loss_kernel, cudaFuncAttributeMaxDynamicSharedMemorySize, SMEM_TOTAL);
    prep_kernel<<<(BATCH*NPTS)/8, 256>>>(pts, f1, f2);
    dim3 grid(NIT, BATCH);
    loss_kernel<<<grid, 256, SMEM_TOTAL>>>(wts);
    reduce_kernel<<<1, 128>>>(out);
}

// round 8
// speedup vs baseline: 1.1135x; 1.0774x over previous
#include <cuda_runtime.h>
#include <cuda_bf16.h>
#include <cstdint>

#define BATCH 4
#define NPTS  4096
#define DIM   64
#define LOG2E 1.4426950408889634f
#define SC_F  24.0224478f          // sqrt(log2e)/0.05
#define TWOL  2.8853900817779268f  // 2*log2e

#define BM 64
#define BN 64
#define NJT (NPTS/BN)   // 64
#define NIT (NPTS/BM)   // 64

#define ROWB 272                    // 256B packed row + 16B pad
#define OFF_A 0
#define SZ_A  (64*ROWB)             // 17408
#define OFF_B (SZ_A)                // 17408
#define SZ_BB (64*ROWB)             // 17408
#define OFF_P (OFF_B + 2*SZ_BB)     // 52224
#define SZ_P  1024
#define OFF_M (OFF_P + 4*SZ_P)      // 56320
#define OFF_R (OFF_M + 3*64*6*4)    // 60928
#define SMEM_TOTAL (OFF_R + 64)     // 60992

// scratch (no allocation allowed)
__device__ __align__(16) uint32_t g_pk1[BATCH*NPTS*64]; // [hi64|lo64] bf16, f1*2log2e
__device__ __align__(16) uint32_t g_pk2[BATCH*NPTS*64]; // [hi64|lo64] bf16, f2 raw
__device__ __align__(16) float4   g_pi[BATCH*NPTS];     // coords*SC
__device__ __align__(16) float4   g_pj[BATCH*NPTS];     // coords*SC, w = log2e*||f2||^2
__device__ float g_partial[BATCH*NIT];

__device__ __forceinline__ float ex2(float x){
    float y; asm("ex2.approx.ftz.f32 %0, %1;" : "=f"(y) : "f"(x)); return y;
}
__device__ __forceinline__ void cpa16(uint32_t dst, const void* src){
    asm volatile("cp.async.cg.shared.global [%0], [%1], 16;\n" :: "r"(dst), "l"(src));
}
__device__ __forceinline__ void ldmx4(uint32_t& r0,uint32_t& r1,uint32_t& r2,uint32_t& r3, uint32_t a){
    asm volatile("ldmatrix.sync.aligned.m8n8.x4.shared.b16 {%0,%1,%2,%3}, [%4];\n"
                 : "=r"(r0),"=r"(r1),"=r"(r2),"=r"(r3) : "r"(a));
}
__device__ __forceinline__ void mma16816(float* c, const uint32_t* a, uint32_t b0, uint32_t b1){
    asm volatile("mma.sync.aligned.m16n8k16.row.col.f32.bf16.bf16.f32 "
                 "{%0,%1,%2,%3}, {%4,%5,%6,%7}, {%8,%9}, {%0,%1,%2,%3};\n"
                 : "+f"(c[0]),"+f"(c[1]),"+f"(c[2]),"+f"(c[3])
                 : "r"(a[0]),"r"(a[1]),"r"(a[2]),"r"(a[3]), "r"(b0),"r"(b1));
}

// ---------------------------------------------------------------------------
__global__ void prep_kernel(const float* __restrict__ pts,
                            const float* __restrict__ f1,
                            const float* __restrict__ f2)
{
    int gw   = (blockIdx.x*blockDim.x + threadIdx.x) >> 5;
    int lane = threadIdx.x & 31;
    if (gw >= BATCH*NPTS) return;
    const float* r1 = f1 + (size_t)gw*DIM;
    const float* r2 = f2 + (size_t)gw*DIM;
    float a0 = r1[lane], a1 = r1[lane+32];
    float b0 = r2[lane], b1 = r2[lane+32];
    float n2 = b0*b0 + b1*b1;
    #pragma unroll
    for (int o=16;o>=1;o>>=1) n2 += __shfl_xor_sync(~0u,n2,o);

    float s0 = a0*TWOL, s1 = a1*TWOL;
    __nv_bfloat16 h0=__float2bfloat16(s0), h1=__float2bfloat16(s1);
    __nv_bfloat16 l0=__float2bfloat16(s0-__bfloat162float(h0));
    __nv_bfloat16 l1=__float2bfloat16(s1-__bfloat162float(h1));
    __nv_bfloat16* o1 = (__nv_bfloat16*)(g_pk1 + (size_t)gw*64);
    o1[lane]=h0; o1[32+lane]=h1; o1[64+lane]=l0; o1[96+lane]=l1;

    __nv_bfloat16 H0=__float2bfloat16(b0), H1=__float2bfloat16(b1);
    __nv_bfloat16 L0=__float2bfloat16(b0-__bfloat162float(H0));
    __nv_bfloat16 L1=__float2bfloat16(b1-__bfloat162float(H1));
    __nv_bfloat16* o2 = (__nv_bfloat16*)(g_pk2 + (size_t)gw*64);
    o2[lane]=H0; o2[32+lane]=H1; o2[64+lane]=L0; o2[96+lane]=L1;

    if (lane==0){
        float px = pts[(size_t)gw*3+0]*SC_F;
        float py = pts[(size_t)gw*3+1]*SC_F;
        float pz = pts[(size_t)gw*3+2]*SC_F;
        g_pi[gw] = make_float4(px,py,pz,0.0f);
        g_pj[gw] = make_float4(px,py,pz,n2*LOG2E);
    }
}

// ---------------------------------------------------------------------------
// loss kernel: BM=64 x BN=64 tiles, 256 thr = 8 warps as 2 (wy) x 4 (wx).
// Warp tile 32 rows x 16 cols. occ=2 via launch_bounds -> TLP pipe overlap.
// ---------------------------------------------------------------------------
__global__ __launch_bounds__(256,2)
void loss_kernel(const float* __restrict__ wts)
{
    extern __shared__ __align__(16) char smem[];
    const uint32_t sb = (uint32_t)__cvta_generic_to_shared(smem);
    const int b  = blockIdx.y;
    const int i0 = blockIdx.x*BM;
    const int tid = threadIdx.x;
    const int w = tid>>5, lane = tid&31;
    const int wy = w>>2, wx = w&3;
    const int g = lane>>2, tig = lane&3;

    // prologue: A + B0 + P0 (group0), B1 + P1 (group1)
    {
        const char* gA  = (const char*)(g_pk1 + (size_t)(b*NPTS+i0)*64);
        const char* gB0 = (const char*)(g_pk2 + (size_t)(b*NPTS)*64);
        #pragma unroll
        for(int q=0;q<4;q++){
            int idx=q*256+tid, r=idx>>4, c=idx&15;
            cpa16(sb + OFF_A + r*ROWB + c*16, gA + r*256 + c*16);
            cpa16(sb + OFF_B + r*ROWB + c*16, gB0 + r*256 + c*16);
        }
        if (tid<64) cpa16(sb + OFF_P + tid*16, (const char*)(g_pj + b*NPTS + tid));
        asm volatile("cp.async.commit_group;\n");
        const char* gB1 = (const char*)(g_pk2 + (size_t)(b*NPTS + BN)*64);
        #pragma unroll
        for(int q=0;q<4;q++){
            int idx=q*256+tid, r=idx>>4, c=idx&15;
            cpa16(sb + OFF_B + SZ_BB + r*ROWB + c*16, gB1 + r*256 + c*16);
        }
        if (tid<64) cpa16(sb + OFF_P + SZ_P + tid*16, (const char*)(g_pj + b*NPTS + BN + tid));
        asm volatile("cp.async.commit_group;\n");
    }

    const uint32_t aAddr = sb + OFF_A + (wy*32 + (lane&15))*ROWB + (lane>>4)*16;
    const int bn_row = (lane&7) + (((lane>>4)&1)<<3);
    const uint32_t bk16 = ((lane>>3)&1)*16;
    const uint32_t pBbase = sb + OFF_B + wx*16*ROWB;

    float x2x[4],x2y[4],x2z[4],nni[4];
    #pragma unroll
    for(int si=0;si<4;si++){
        int mb=si>>1, rp=si&1;
        int rl = wy*32 + mb*16 + rp*8 + g;
        float4 v = g_pi[b*NPTS + i0 + rl];
        x2x[si]=v.x+v.x; x2y[si]=v.y+v.y; x2z[si]=v.z+v.z;
        nni[si]=-fmaf(v.x,v.x, fmaf(v.y,v.y, v.z*v.z));
    }
    float m2s[4],Z1s[4],Z2s[4],As[4],Bs[4],Cs[4];
    #pragma unroll
    for(int si=0;si<4;si++){ m2s[si]=-3.0e38f; Z1s[si]=0.f;Z2s[si]=0.f;As[si]=0.f;Bs[si]=0.f;Cs[si]=0.f; }

    asm volatile("cp.async.wait_group 1;\n" ::: "memory");
    __syncthreads();

    for(int jt=0; jt<NJT; jt++){
        const int buf = jt&1;
        // ---- MMA over current tile: 4 k16-chunks x {HH,HL,LH} ----
        float acc[2][2][4];
        #pragma unroll
        for(int mb=0;mb<2;mb++)
            #pragma unroll
            for(int nb=0;nb<2;nb++)
                #pragma unroll
                for(int q=0;q<4;q++) acc[mb][nb][q]=0.f;
        {
            const uint32_t pB = pBbase + buf*SZ_BB;
            #pragma unroll
            for(int c=0;c<4;c++){
                const int oh = c<<5;
                const int ol = 128 + (c<<5);
                uint32_t ah[2][4], al[2][4], bh[4], bl[4];
                ldmx4(ah[0][0],ah[0][1],ah[0][2],ah[0][3], aAddr + oh);
                ldmx4(ah[1][0],ah[1][1],ah[1][2],ah[1][3], aAddr + 16*ROWB + oh);
                ldmx4(al[0][0],al[0][1],al[0][2],al[0][3], aAddr + ol);
                ldmx4(al[1][0],al[1][1],al[1][2],al[1][3], aAddr + 16*ROWB + ol);
                uint32_t ba = pB + bn_row*ROWB + bk16;
                ldmx4(bh[0],bh[1],bh[2],bh[3], ba + oh);
                ldmx4(bl[0],bl[1],bl[2],bl[3], ba + ol);
                #pragma unroll
                for(int mb=0;mb<2;mb++){
                    mma16816(acc[mb][0], ah[mb], bh[0], bh[1]);
                    mma16816(acc[mb][1], ah[mb], bh[2], bh[3]);
                    mma16816(acc[mb][0], ah[mb], bl[0], bl[1]);
                    mma16816(acc[mb][1], ah[mb], bl[2], bl[3]);
                    mma16816(acc[mb][0], al[mb], bh[0], bh[1]);
                    mma16816(acc[mb][1], al[mb], bh[2], bh[3]);
                }
            }
        }

        // sync off the B buffer we just read, then prefetch jt+2 into it
        if (jt+1 < NJT){
            asm volatile("cp.async.wait_group 0;\n" ::: "memory");
        }
        __syncthreads();
        if (jt+2 < NJT){
            const char* gB = (const char*)(g_pk2 + (size_t)(b*NPTS + (jt+2)*BN)*64);
            const uint32_t dstB = sb + OFF_B + ((jt+2)&1)*SZ_BB;
            #pragma unroll
            for(int q=0;q<4;q++){
                int idx=q*256+tid, r=idx>>4, c=idx&15;
                cpa16(dstB + r*ROWB + c*16, gB + r*256 + c*16);
            }
            if (tid<64) cpa16(sb + OFF_P + ((jt+2)&3)*SZ_P + tid*16,
                              (const char*)(g_pj + b*NPTS + (jt+2)*BN + tid));
            asm volatile("cp.async.commit_group;\n");
        }

        // ---- epilogue on current tile ----
        {
            const float*  pW = (const float*)(smem + OFF_P + (jt&3)*SZ_P);
            const float4* pP = (const float4*)pW;
            // per-thread min of cn2 over my 4 cols (safe per-tile max bound)
            float mn = 3.0e38f;
            #pragma unroll
            for(int nb=0;nb<2;nb++){
                int c0 = wx*16 + nb*8 + tig*2;
                mn = fminf(mn, fminf(pW[c0*4+3], pW[(c0+1)*4+3]));
            }
            #pragma unroll
            for(int si=0;si<4;si++){
                int mb=si>>1, rp=si&1;
                float mx = fmaxf(fmaxf(acc[mb][0][rp*2], acc[mb][0][rp*2+1]),
                                 fmaxf(acc[mb][1][rp*2], acc[mb][1][rp*2+1]));
                float m2n = fmaxf(m2s[si], mx - mn);
                float c2 = ex2(m2s[si] - m2n);
                Z2s[si]*=c2; Cs[si]*=c2; Bs[si]*=c2*c2; m2s[si]=m2n;
            }
            #pragma unroll
            for(int nb=0;nb<2;nb++){
                #pragma unroll
                for(int qq=0;qq<2;qq++){
                    int c = wx*16 + nb*8 + tig*2 + qq;
                    float4 v = pP[c];
                    float njc = fmaf(v.x,v.x, fmaf(v.y,v.y, v.z*v.z));
                    #pragma unroll
                    for(int si=0;si<4;si++){
                        int mb=si>>1, rp=si&1;
                        float t = fmaf(x2x[si], v.x, fmaf(x2y[si], v.y,
                                  fmaf(x2z[si], v.z, nni[si] - njc)));
                        float e1 = ex2(t);
                        float e2 = ex2((acc[mb][nb][rp*2+qq] - v.w) - m2s[si]);
                        Z1s[si]+=e1; As[si]=fmaf(e1,e1,As[si]);
                        Z2s[si]+=e2; Bs[si]=fmaf(e2,e2,Bs[si]);
                        Cs[si]=fmaf(e1,e2,Cs[si]);
                    }
                }
            }
        }
    }

    // ---- merge 4 tig-lanes per row ----
    #pragma unroll
    for(int si=0;si<4;si++){
        #pragma unroll
        for(int off=1; off<=2; off<<=1){
            float om = __shfl_xor_sync(~0u, m2s[si], off);
            float oZ2= __shfl_xor_sync(~0u, Z2s[si], off);
            float oB = __shfl_xor_sync(~0u, Bs[si], off);
            float oC = __shfl_xor_sync(~0u, Cs[si], off);
            float oZ1= __shfl_xor_sync(~0u, Z1s[si], off);
            float oA = __shfl_xor_sync(~0u, As[si], off);
            float nm = fmaxf(m2s[si], om);
            float c = ex2(m2s[si]-nm), d = ex2(om-nm);
            Z2s[si]=Z2s[si]*c + oZ2*d;
            Bs[si]=Bs[si]*c*c + oB*d*d;
            Cs[si]=Cs[si]*c + oC*d;
            Z1s[si]+=oZ1; As[si]+=oA;
            m2s[si]=nm;
        }
    }
    // ---- merge across wx=0..3 (4 warps share rows) via smem ----
    float* sM = (float*)(smem + OFF_M);
    float* sR = (float*)(smem + OFF_R);
    if (wx>0 && tig==0){
        #pragma unroll
        for(int si=0;si<4;si++){
            int mb=si>>1, rp=si&1;
            int rl = wy*32 + mb*16 + rp*8 + g;
            float* p = sM + ((wx-1)*64 + rl)*6;
            p[0]=m2s[si]; p[1]=Z2s[si]; p[2]=Bs[si]; p[3]=Cs[si]; p[4]=Z1s[si]; p[5]=As[si];
        }
    }
    __syncthreads();
    float wacc = 0.0f;
    if (wx==0 && tig==0){
        #pragma unroll
        for(int si=0;si<4;si++){
            int mb=si>>1, rp=si&1;
            int rl = wy*32 + mb*16 + rp*8 + g;
            float M=m2s[si], Z2=Z2s[si], Bv=Bs[si], Cv=Cs[si], Z1=Z1s[si], Av=As[si];
            #pragma unroll
            for(int s=0;s<3;s++){
                const float* p = sM + (s*64 + rl)*6;
                float om=p[0], oZ2=p[1], oB=p[2], oC=p[3], oZ1=p[4], oA=p[5];
                float nm = fmaxf(M, om);
                float c = ex2(M-nm), d = ex2(om-nm);
                Z2 = Z2*c + oZ2*d;
                Bv = Bv*c*c + oB*d*d;
                Cv = Cv*c + oC*d;
                Z1 += oZ1; Av += oA;
                M = nm;
            }
            float i1 = 1.0f/Z1, i2 = 1.0f/Z2;
            float loss = Av*i1*i1 - 2.0f*Cv*i1*i2 + Bv*i2*i2;
            wacc += wts[b*NPTS + i0 + rl] * loss;
        }
    }
    #pragma unroll
    for(int off=16; off>=1; off>>=1) wacc += __shfl_xor_sync(~0u, wacc, off);
    if (wx==0 && lane==0) sR[wy] = wacc;
    __syncthreads();
    if (tid==0)
        g_partial[b*NIT + blockIdx.x] = sR[0] + sR[1];
}

// ---------------------------------------------------------------------------
__global__ void reduce_kernel(float* __restrict__ out)
{
    int b    = threadIdx.x >> 5;
    int lane = threadIdx.x & 31;
    float s = g_partial[b*NIT + lane] + g_partial[b*NIT + 32 + lane];
    #pragma unroll
    for(int off=16; off>=1; off>>=1) s += __shfl_xor_sync(~0u, s, off);
    if (lane==0) out[b] = s;
}

// ---------------------------------------------------------------------------
extern "C" void kernel_launch(void* const* d_in, const int* in_sizes, int n_in,
                              void* d_out, int out_size)
{
    const float* pts = (const float*)d_in[0];
    const float* wts = (const float*)d_in[1];
    const float* f1  = (const float*)d_in[2];
    const float* f2  = (const float*)d_in[3];
    float* out = (float*)d_out;

    cudaFuncSetAttribute(loss_kernel, cudaFuncAttributeMaxDynamicSharedMemorySize, SMEM_TOTAL);
    prep_kernel<<<(BATCH*NPTS)/8, 256>>>(pts, f1, f2);
    dim3 grid(NIT, BATCH);
    loss_kernel<<<grid, 256, SMEM_TOTAL>>>(wts);
    reduce_kernel<<<1, 128>>>(out);
}